// round 15
// baseline (speedup 1.0000x reference)
#include <cuda_runtime.h>
#include <cuda_bf16.h>

#define KS 7
#define KK 49
#define TPB 128

// Keys bicubic (a=-0.5), branch-free: cubic(x) = u^2(1-2u) + v^2(4v-2),
// u = sat(1-|x|), v = sat(1-|x|/2). C1-continuous, EXACTLY zero for |x|>=2.
__device__ __forceinline__ float cubic_w(float x) {
    float ax = fabsf(x);
    float u = __saturatef(1.0f - ax);
    float v = __saturatef(fmaf(ax, -0.5f, 1.0f));
    return fmaf(v * v, fmaf(v, 4.0f, -2.0f), (u * u) * fmaf(u, -2.0f, 1.0f));
}

// Evaluate the NX x NY active window at per-lane offsets (k0x, k0y); all
// slots outside the window are provably zero (|arg| >= 2). Exact math.
template<int NX, int NY>
__device__ __forceinline__ void eval_win(float Axx, float Axy, float Cxx, float Dyy,
                                         float fx, float fy, int k0x, int k0y,
                                         float* wrow)
{
    float A[NX], Cc[NX];
    #pragma unroll
    for (int i = 0; i < NX; i++) {
        float wx = fx + 2.5f - (float)(k0x + i);
        A[i]  = Axx * wx;
        Cc[i] = Cxx * wx;
    }

    // zero out-of-window rows (full 7) -- trip count uniform, row idx per-lane
    #pragma unroll
    for (int r = 0; r < KS - NY; r++) {
        int row = (r < k0y) ? r : r + NY;
        float* z = wrow + row * KS;
        #pragma unroll
        for (int c = 0; c < KS; c++) z[c] = 0.0f;
    }
    // zero out-of-window cols inside window rows
    #pragma unroll
    for (int iy = 0; iy < NY; iy++) {
        float* z = wrow + (k0y + iy) * KS;
        #pragma unroll
        for (int c = 0; c < KS - NX; c++) {
            int col = (c < k0x) ? c : c + NX;
            z[col] = 0.0f;
        }
    }

    if constexpr (NX * NY <= 28) {
        // register-buffered: single normalized store
        float w[NX * NY];
        float s0 = 0.0f, s1 = 0.0f;
        #pragma unroll
        for (int iy = 0; iy < NY; iy++) {
            float wy = fy + 2.5f - (float)(k0y + iy);
            float Bk = Axy * wy;
            float Dk = Dyy * wy;
            #pragma unroll
            for (int ix = 0; ix < NX; ix++) {
                float v = cubic_w(A[ix] + Bk) * cubic_w(Cc[ix] + Dk);
                w[iy * NX + ix] = v;
                if (ix & 1) s1 += v; else s0 += v;
            }
        }
        const float inv = __frcp_rn(s0 + s1);
        #pragma unroll
        for (int iy = 0; iy < NY; iy++) {
            float* r = wrow + (k0y + iy) * KS + k0x;
            #pragma unroll
            for (int ix = 0; ix < NX; ix++) r[ix] = w[iy * NX + ix] * inv;
        }
    } else {
        // streamed: store raw, renormalize window slots
        float s0 = 0.0f, s1 = 0.0f;
        #pragma unroll
        for (int iy = 0; iy < NY; iy++) {
            float wy = fy + 2.5f - (float)(k0y + iy);
            float Bk = Axy * wy;
            float Dk = Dyy * wy;
            float* r = wrow + (k0y + iy) * KS + k0x;
            #pragma unroll
            for (int ix = 0; ix < NX; ix++) {
                float v = cubic_w(A[ix] + Bk) * cubic_w(Cc[ix] + Dk);
                if (ix & 1) s1 += v; else s0 += v;
                r[ix] = v;
            }
        }
        const float inv = __frcp_rn(s0 + s1);
        #pragma unroll
        for (int iy = 0; iy < NY; iy++) {
            float* r = wrow + (k0y + iy) * KS + k0x;
            #pragma unroll
            for (int ix = 0; ix < NX; ix++) r[ix] *= inv;
        }
    }
}

__global__ __launch_bounds__(TPB, 8)
void kest_kernel(const float* __restrict__ m,
                 const float* __restrict__ grid,
                 const int*   __restrict__ Wp,
                 const int*   __restrict__ yi,
                 float*       __restrict__ out,
                 int N)
{
    __shared__ __align__(16) float w_s[TPB * KK];

    const int t = threadIdx.x;
    const int lane = t & 31;
    const int warp = t >> 5;
    const int n = blockIdx.x * TPB + t;
    const int n_eff = min(n, N - 1);      // all lanes compute; keeps votes uniform

    const float m00 = __ldg(m + 0), m01 = __ldg(m + 1), m02 = __ldg(m + 2);
    const float m10 = __ldg(m + 3), m11 = __ldg(m + 4), m12 = __ldg(m + 5);
    const float m20 = __ldg(m + 6), m21 = __ldg(m + 7), m22 = __ldg(m + 8);
    const unsigned W = (unsigned)__ldg(Wp);

    const unsigned p = (unsigned)__ldg(yi + n_eff);
    unsigned pxi, pyi_;
    if ((W & (W - 1u)) == 0u) {           // uniform branch
        const int sh = __ffs((int)W) - 1;
        pxi = p & (W - 1u);
        pyi_ = p >> sh;
    } else {
        pyi_ = p / W;
        pxi = p - pyi_ * W;
    }
    const float px = (float)pxi;
    const float py = (float)pyi_;

    // Analytic central differences of the homography map (algebraically equal
    // to the reference's (pr-pl), (pb-pt) finite differences).
    const float X0 = fmaf(m00, px, fmaf(m01, py, m02));
    const float Y0 = fmaf(m10, px, fmaf(m11, py, m12));
    const float Z0 = fmaf(m20, px, fmaf(m21, py, m22));
    const float Z2 = Z0 * Z0;
    const float da = fmaf(m21, -0.25f * m21, Z2);
    const float db = fmaf(m20, -0.25f * m20, Z2);
    const float rab = __frcp_rn(da * db);
    const float idu = rab * db;
    const float idv = rab * da;

    float du0 = (m01 * Z0 - m21 * X0) * idu;
    float du1 = (m11 * Z0 - m21 * Y0) * idu;
    float dv0 = (m00 * Z0 - m20 * X0) * idv;
    float dv1 = (m10 * Z0 - m20 * Y0) * idv;

    // branch-free |du| >= 1 regularization via rsqrt
    float s  = fmaf(du0, du0, du1 * du1);
    float rs = __frsqrt_rn(s);
    float len = s * rs;
    bool cnd = len < 1.0f;
    float sc = cnd ? rs : 1.0f;
    du0 *= sc; du1 *= sc;
    float rlen_du = cnd ? 1.0f : rs;

    float s2  = fmaf(dv0, dv0, dv1 * dv1);
    float rs2 = __frsqrt_rn(s2);
    float len2 = s2 * rs2;
    bool cnd2 = len2 < 1.0f;
    float sc2 = cnd2 ? rs2 : 1.0f;
    dv0 *= sc2; dv1 *= sc2;
    float rlen_dv = cnd2 ? 1.0f : rs2;

    const float det  = du0 * dv1 - du1 * dv0;
    const float rdet = __frcp_rn(det);
    const float ild  = rdet * rlen_du;
    const float ilv  = rdet * rlen_dv;

    const float Axx = du0 * dv1 * ild - du1 * dv0 * ilv;
    const float Axy = du0 * du1 * (ilv - ild);
    const float Cxx = dv0 * dv1 * (ild - ilv);
    const float Dyy = dv1 * du0 * ilv - dv0 * du1 * ild;

    const float gx = __ldg(grid + n_eff);
    const float gy = __ldg(grid + N + n_eff);
    const float fx = (gx + 0.5f) - floorf(gx + 0.5f);
    const float fy = (gy + 0.5f) - floorf(gy + 0.5f);

    float* wrow = &w_s[t * KK];

    // Window reach per direction: all taps with |Axx*wx + cross| >= 2 are zero.
    // reach = (2 + 3.5|Axy|)/|Axx| (+eps safety). Guaranteed window widths:
    //   reach <= 2.0 -> 4 taps;  reach <= 2.5 -> 5 taps;  else 7.
    const float reachx = (2.0002f + 3.5f * fabsf(Axy)) * __frcp_rn(fabsf(Axx));
    const float reachy = (2.0002f + 3.5f * fabsf(Cxx)) * __frcp_rn(fabsf(Dyy));
    const bool x4 = __all_sync(0xffffffffu, reachx <= 2.0f);
    const bool x5 = __all_sync(0xffffffffu, reachx <= 2.5f);
    const bool y4 = __all_sync(0xffffffffu, reachy <= 2.0f);
    const bool y5 = __all_sync(0xffffffffu, reachy <= 2.5f);
    const int NXc = x4 ? 4 : (x5 ? 5 : 7);
    const int NYc = y4 ? 4 : (y5 ? 5 : 7);

    // per-lane window offsets (k0 in [0, 7-N]); valid since reach <= (N+1)/2
    int k0x = 0, k0y = 0;
    if (NXc < 7) {
        float f = ceilf(fx + 2.5f + reachx - (float)NXc);
        k0x = min(max((int)f, 0), KS - NXc);
    }
    if (NYc < 7) {
        float f = ceilf(fy + 2.5f + reachy - (float)NYc);
        k0y = min(max((int)f, 0), KS - NYc);
    }

    if (NXc == 4) {
        if (NYc == 4)      eval_win<4,4>(Axx, Axy, Cxx, Dyy, fx, fy, k0x, k0y, wrow);
        else if (NYc == 5) eval_win<4,5>(Axx, Axy, Cxx, Dyy, fx, fy, k0x, k0y, wrow);
        else               eval_win<4,7>(Axx, Axy, Cxx, Dyy, fx, fy, k0x, k0y, wrow);
    } else if (NXc == 5) {
        if (NYc == 4)      eval_win<5,4>(Axx, Axy, Cxx, Dyy, fx, fy, k0x, k0y, wrow);
        else if (NYc == 5) eval_win<5,5>(Axx, Axy, Cxx, Dyy, fx, fy, k0x, k0y, wrow);
        else               eval_win<5,7>(Axx, Axy, Cxx, Dyy, fx, fy, k0x, k0y, wrow);
    } else {
        if (NYc == 4)      eval_win<7,4>(Axx, Axy, Cxx, Dyy, fx, fy, k0x, k0y, wrow);
        else if (NYc == 5) eval_win<7,5>(Axx, Axy, Cxx, Dyy, fx, fy, k0x, k0y, wrow);
        else               eval_win<7,7>(Axx, Axy, Cxx, Dyy, fx, fy, k0x, k0y, wrow);
    }

    // ---- per-warp write-out: bulk async copy of this warp's 32 rows ----
    __syncwarp();
    const long long blockBase = (long long)blockIdx.x * (TPB * KK);
    const int warpPixBase = blockIdx.x * TPB + warp * 32;
    const int pix = min(32, N - warpPixBase);
    if (pix == 32) {
        if (lane == 0) {
            unsigned saddr = (unsigned)__cvta_generic_to_shared(w_s + warp * 32 * KK);
            asm volatile("fence.proxy.async.shared::cta;" ::: "memory");
            asm volatile("cp.async.bulk.global.shared::cta.bulk_group [%0], [%1], %2;"
                         :: "l"(out + blockBase + warp * 32 * KK), "r"(saddr),
                            "r"((unsigned)(32 * KK * 4))
                         : "memory");
            asm volatile("cp.async.bulk.commit_group;" ::: "memory");
            asm volatile("cp.async.bulk.wait_group.read 0;" ::: "memory");
        }
    } else if (pix > 0) {
        const int cnt = pix * KK;
        const int off = warp * 32 * KK;
        for (int i = lane; i < cnt; i += 32) out[blockBase + off + i] = w_s[off + i];
    }
}

extern "C" void kernel_launch(void* const* d_in, const int* in_sizes, int n_in,
                              void* d_out, int out_size) {
    // metadata order: m_inverse (9), grid (2N), H (1), W (1), yi (N)
    const float* m    = (const float*)d_in[0];
    const float* grid = (const float*)d_in[1];
    const int*   Wp   = (const int*)d_in[3];
    const int*   yi   = (const int*)d_in[4];
    float* out = (float*)d_out;

    const int N = in_sizes[4];
    const int blocks = (N + TPB - 1) / TPB;
    kest_kernel<<<blocks, TPB>>>(m, grid, Wp, yi, out, N);
}

// round 16
// speedup vs baseline: 1.0810x; 1.0810x over previous
#include <cuda_runtime.h>
#include <cuda_bf16.h>

#define KS 7
#define KK 49
#define TPB 128
#define ABSMASK 0x7FFFFFFF7FFFFFFFULL

typedef unsigned long long u64;

__device__ __forceinline__ u64 pk2(float lo, float hi) {
    u64 r; asm("mov.b64 %0, {%1, %2};" : "=l"(r) : "f"(lo), "f"(hi)); return r;
}
__device__ __forceinline__ void unpk2(u64 a, float& lo, float& hi) {
    asm("mov.b64 {%0, %1}, %2;" : "=f"(lo), "=f"(hi) : "l"(a));
}
__device__ __forceinline__ u64 fma2(u64 a, u64 b, u64 c) {
    u64 d; asm("fma.rn.f32x2 %0, %1, %2, %3;" : "=l"(d) : "l"(a), "l"(b), "l"(c)); return d;
}
__device__ __forceinline__ u64 add2(u64 a, u64 b) {
    u64 d; asm("add.rn.f32x2 %0, %1, %2;" : "=l"(d) : "l"(a), "l"(b)); return d;
}
__device__ __forceinline__ u64 mul2(u64 a, u64 b) {
    u64 d; asm("mul.rn.f32x2 %0, %1, %2;" : "=l"(d) : "l"(a), "l"(b)); return d;
}

// Packed pair of Keys cubics (a=-0.5), scaled by exactly 4 (cancels in
// normalization). max(x,0) emulated as x+|x| (=2*max), absorbed into the
// scale:  cubicS(x) = U^2(1-U) + 2V^2(V-1),  U=2*sat(1-|x|), V=2*sat(1-|x|/2).
struct C2K { u64 c1, cm1, cmh, c2, cm2; };

__device__ __forceinline__ float cubic2(u64 arg, const C2K& K) {
    u64 a  = arg & ABSMASK;            // |x| both halves (ALU)
    u64 um = fma2(a, K.cm1, K.c1);     // 1-|x|
    u64 vm = fma2(a, K.cmh, K.c1);     // 1-|x|/2
    u64 U  = add2(um, um & ABSMASK);   // 2*max(um,0)
    u64 V  = add2(vm, vm & ABSMASK);   // 2*max(vm,0)
    u64 pU = fma2(U, K.cm1, K.c1);     // 1-U
    u64 pV = fma2(V, K.c2, K.cm2);     // 2V-2
    u64 UU = mul2(U, U);
    u64 VV = mul2(V, V);
    u64 t  = mul2(UU, pU);
    u64 r  = fma2(VV, pV, t);          // (cubicS_x, cubicS_y)
    float cx, cy; unpk2(r, cx, cy);
    return cx * cy;                    // 16*w ; scale cancels in normalization
}

__global__ __launch_bounds__(TPB, 8)
void kest_kernel(const float* __restrict__ m,
                 const float* __restrict__ grid,
                 const int*   __restrict__ Wp,
                 const int*   __restrict__ yi,
                 float*       __restrict__ out,
                 int N)
{
    __shared__ __align__(16) float w_s[TPB * KK];

    const int t = threadIdx.x;
    const int lane = t & 31;
    const int warp = t >> 5;
    const int n = blockIdx.x * TPB + t;
    const int n_eff = min(n, N - 1);      // all lanes compute; keeps votes uniform

    const float m00 = __ldg(m + 0), m01 = __ldg(m + 1), m02 = __ldg(m + 2);
    const float m10 = __ldg(m + 3), m11 = __ldg(m + 4), m12 = __ldg(m + 5);
    const float m20 = __ldg(m + 6), m21 = __ldg(m + 7), m22 = __ldg(m + 8);
    const unsigned W = (unsigned)__ldg(Wp);

    const unsigned p = (unsigned)__ldg(yi + n_eff);
    unsigned pxi, pyi_;
    if ((W & (W - 1u)) == 0u) {           // uniform branch
        const int sh = __ffs((int)W) - 1;
        pxi = p & (W - 1u);
        pyi_ = p >> sh;
    } else {
        pyi_ = p / W;
        pxi = p - pyi_ * W;
    }
    const float px = (float)pxi;
    const float py = (float)pyi_;

    // Analytic central differences of the homography map (algebraically equal
    // to the reference's (pr-pl), (pb-pt) finite differences).
    const float X0 = fmaf(m00, px, fmaf(m01, py, m02));
    const float Y0 = fmaf(m10, px, fmaf(m11, py, m12));
    const float Z0 = fmaf(m20, px, fmaf(m21, py, m22));
    const float Z2 = Z0 * Z0;
    const float da = fmaf(m21, -0.25f * m21, Z2);
    const float db = fmaf(m20, -0.25f * m20, Z2);
    const float rab = __frcp_rn(da * db);
    const float idu = rab * db;
    const float idv = rab * da;

    float du0 = (m01 * Z0 - m21 * X0) * idu;
    float du1 = (m11 * Z0 - m21 * Y0) * idu;
    float dv0 = (m00 * Z0 - m20 * X0) * idv;
    float dv1 = (m10 * Z0 - m20 * Y0) * idv;

    // branch-free |du| >= 1 regularization via rsqrt
    float s  = fmaf(du0, du0, du1 * du1);
    float rs = __frsqrt_rn(s);
    float len = s * rs;
    bool cnd = len < 1.0f;
    float sc = cnd ? rs : 1.0f;
    du0 *= sc; du1 *= sc;
    float rlen_du = cnd ? 1.0f : rs;

    float s2  = fmaf(dv0, dv0, dv1 * dv1);
    float rs2 = __frsqrt_rn(s2);
    float len2 = s2 * rs2;
    bool cnd2 = len2 < 1.0f;
    float sc2 = cnd2 ? rs2 : 1.0f;
    dv0 *= sc2; dv1 *= sc2;
    float rlen_dv = cnd2 ? 1.0f : rs2;

    const float det  = du0 * dv1 - du1 * dv0;
    const float rdet = __frcp_rn(det);
    const float ild  = rdet * rlen_du;
    const float ilv  = rdet * rlen_dv;

    const float Axx = du0 * dv1 * ild - du1 * dv0 * ilv;
    const float Axy = du0 * du1 * (ilv - ild);
    const float Cxx = dv0 * dv1 * (ild - ilv);
    const float Dyy = dv1 * du0 * ilv - dv0 * du1 * ild;

    const float gx = __ldg(grid + n_eff);
    const float gy = __ldg(grid + N + n_eff);
    const float fx = (gx + 0.5f) - floorf(gx + 0.5f);
    const float fy = (gy + 0.5f) - floorf(gy + 0.5f);

    float* wrow = &w_s[t * KK];

    // packed constants (loop-invariant)
    C2K K;
    K.c1  = pk2( 1.0f,  1.0f);
    K.cm1 = pk2(-1.0f, -1.0f);
    K.cmh = pk2(-0.5f, -0.5f);
    K.c2  = pk2( 2.0f,  2.0f);
    K.cm2 = pk2(-2.0f, -2.0f);

    // 5x5 support condition (EXACT): taps 0,6 have |main arg| >= 0.85*2.5 = 2.125;
    // cross perturbation <= 3.5*max(|Axy|,|Cxx|) <= 0.125 keeps |arg| >= 2 -> cubic == 0.
    const float crossmax = fmaxf(fabsf(Axy), fabsf(Cxx)) * 3.5f;
    const bool small = (fabsf(Axx) >= 0.85f) & (fabsf(Dyy) >= 0.85f) & (crossmax <= 0.125f);
    const bool warp_small = __all_sync(0xffffffffu, small);

    if (warp_small) {
        // ---- exact 5x5 core (taps k=1..5 both directions); border exactly 0 ----
        u64 ACc[5];
        #pragma unroll
        for (int i = 0; i < 5; i++) {
            float wxk = fx + (1.5f - (float)i);   // k = i+1
            ACc[i] = pk2(Axx * wxk, Cxx * wxk);
        }

        float w[25];
        float sum0 = 0.0f, sum1 = 0.0f;
        #pragma unroll
        for (int iy = 0; iy < 5; iy++) {
            float wyk = fy + (1.5f - (float)iy);
            u64 BD = pk2(Axy * wyk, Dyy * wyk);
            #pragma unroll
            for (int ix = 0; ix < 5; ix++) {
                float v = cubic2(add2(ACc[ix], BD), K);
                w[iy * 5 + ix] = v;
                if (ix & 1) sum1 += v; else sum0 += v;
            }
        }
        const float inv = __frcp_rn(sum0 + sum1);

        // zero border: rows 0,6 and cols 0,6
        #pragma unroll
        for (int j = 0; j < KS; j++) { wrow[j] = 0.0f; wrow[42 + j] = 0.0f; }
        #pragma unroll
        for (int ky = 1; ky <= 5; ky++) { wrow[ky * KS] = 0.0f; wrow[ky * KS + 6] = 0.0f; }

        #pragma unroll
        for (int iy = 0; iy < 5; iy++) {
            float* r = wrow + (iy + 1) * KS + 1;
            #pragma unroll
            for (int ix = 0; ix < 5; ix++) r[ix] = w[iy * 5 + ix] * inv;
        }
    } else {
        // ---- exact 7x7 fallback, streamed ----
        u64 ACc[KS];
        #pragma unroll
        for (int k = 0; k < KS; k++) {
            float wxk = fx + (2.5f - (float)k);
            ACc[k] = pk2(Axx * wxk, Cxx * wxk);
        }
        float sum0 = 0.0f, sum1 = 0.0f;
        #pragma unroll
        for (int ky = 0; ky < KS; ky++) {
            float wyk = fy + (2.5f - (float)ky);
            u64 BD = pk2(Axy * wyk, Dyy * wyk);
            float* r = wrow + ky * KS;
            #pragma unroll
            for (int kx = 0; kx < KS; kx++) {
                float v = cubic2(add2(ACc[kx], BD), K);
                if (kx & 1) sum1 += v; else sum0 += v;
                r[kx] = v;
            }
        }
        const float inv = __frcp_rn(sum0 + sum1);
        #pragma unroll
        for (int j = 0; j < KK; j++) wrow[j] *= inv;
    }

    // ---- per-warp write-out: bulk async copy of this warp's 32 rows ----
    __syncwarp();
    const long long blockBase = (long long)blockIdx.x * (TPB * KK);
    const int warpPixBase = blockIdx.x * TPB + warp * 32;
    const int pix = min(32, N - warpPixBase);
    if (pix == 32) {
        if (lane == 0) {
            unsigned saddr = (unsigned)__cvta_generic_to_shared(w_s + warp * 32 * KK);
            asm volatile("fence.proxy.async.shared::cta;" ::: "memory");
            asm volatile("cp.async.bulk.global.shared::cta.bulk_group [%0], [%1], %2;"
                         :: "l"(out + blockBase + warp * 32 * KK), "r"(saddr),
                            "r"((unsigned)(32 * KK * 4))
                         : "memory");
            asm volatile("cp.async.bulk.commit_group;" ::: "memory");
            asm volatile("cp.async.bulk.wait_group.read 0;" ::: "memory");
        }
    } else if (pix > 0) {
        const int cnt = pix * KK;
        const int off = warp * 32 * KK;
        for (int i = lane; i < cnt; i += 32) out[blockBase + off + i] = w_s[off + i];
    }
}

extern "C" void kernel_launch(void* const* d_in, const int* in_sizes, int n_in,
                              void* d_out, int out_size) {
    // metadata order: m_inverse (9), grid (2N), H (1), W (1), yi (N)
    const float* m    = (const float*)d_in[0];
    const float* grid = (const float*)d_in[1];
    const int*   Wp   = (const int*)d_in[3];
    const int*   yi   = (const int*)d_in[4];
    float* out = (float*)d_out;

    const int N = in_sizes[4];
    const int blocks = (N + TPB - 1) / TPB;
    kest_kernel<<<blocks, TPB>>>(m, grid, Wp, yi, out, N);
}